// round 6
// baseline (speedup 1.0000x reference)
#include <cuda_runtime.h>
#include <math.h>
#include <stdint.h>

#define BQ 128
#define KQ 128
#define VDQ 128
#define ODQ 256
#define EQ 300
#define AQ 512
#define DQ 512
#define VQ 4000
#define TQ 32
#define XDIM 684     // E + VD + OD
#define YDIM 2688    // 512 (dec_att) + 128 (fbeta) + 2048 (hh)
#define GRID_P 256   // persistent grid size
#define NSPLIT 4     // split-K partials

// ------------------------- scratch (device globals) -------------------------
__device__ float g_att1[(size_t)BQ * KQ * AQ];           // 32 MB
__device__ float g_Yp[(size_t)NSPLIT * BQ * YDIM];       // 5.5 MB split-K partials
__device__ float g_h[BQ * DQ];
__device__ float g_c[BQ * DQ];
__device__ float g_x[BQ * XDIM];
__device__ float g_init[BQ * (VDQ + ODQ)];
__device__ float g_hstore[(size_t)TQ * BQ * DQ];         // 8 MB, [t][b][j]
__device__ float g_predsT[(size_t)TQ * BQ * VQ];         // 64 MB, [t][b][v]
__device__ unsigned char g_mask[BQ * KQ];
__device__ unsigned g_bar = 0;
__device__ unsigned g_done = 0;

typedef unsigned long long ull;
__device__ __forceinline__ ull pk2(float x, float y) {
    ull r; asm("mov.b64 %0,{%1,%2};" : "=l"(r) : "f"(x), "f"(y)); return r;
}
__device__ __forceinline__ void fma2(ull& d, ull a, ull b) {
    asm("fma.rn.f32x2 %0,%1,%2,%0;" : "+l"(d) : "l"(a), "l"(b));
}
__device__ __forceinline__ float lo32(ull v) { return __uint_as_float((unsigned)v); }
__device__ __forceinline__ float hi32(ull v) { return __uint_as_float((unsigned)(v >> 32)); }
__device__ __forceinline__ float sigf(float x) { return 1.f / (1.f + expf(-x)); }

// hardened grid barrier (proven in round 4)
__device__ __forceinline__ void grid_bar(unsigned target)
{
    __syncthreads();
    __threadfence();
    if (threadIdx.x == 0) {
        asm volatile("red.release.gpu.global.add.u32 [%0], %1;"
                     :: "l"(&g_bar), "r"(1u) : "memory");
        unsigned v;
        do {
            asm volatile("ld.acquire.gpu.global.u32 %0, [%1];"
                         : "=r"(v) : "l"(&g_bar) : "memory");
        } while (v < target);
    }
    __syncthreads();
}

// guarded float4 loads
__device__ __forceinline__ float4 ld4g_cg(const float* base, int k, int limit) {
    if (k + 4 <= limit) return __ldcg((const float4*)(base + k));
    float4 v = make_float4(0.f, 0.f, 0.f, 0.f);
    if (k + 0 < limit) v.x = __ldcg(base + k + 0);
    if (k + 1 < limit) v.y = __ldcg(base + k + 1);
    if (k + 2 < limit) v.z = __ldcg(base + k + 2);
    if (k + 3 < limit) v.w = __ldcg(base + k + 3);
    return v;
}
__device__ __forceinline__ float4 ld4g_ro(const float* base, int k, int limit) {
    if (k + 4 <= limit) return __ldg((const float4*)(base + k));
    float4 v = make_float4(0.f, 0.f, 0.f, 0.f);
    if (k + 0 < limit) v.x = __ldg(base + k + 0);
    if (k + 1 < limit) v.y = __ldg(base + k + 1);
    if (k + 2 < limit) v.z = __ldg(base + k + 2);
    if (k + 3 < limit) v.w = __ldg(base + k + 3);
    return v;
}

// ------------------------- object mask kernel -------------------------------
__global__ void mask_kernel(const float* __restrict__ obj,
                            const float* __restrict__ center,
                            const float* __restrict__ xyz,
                            float* __restrict__ out_mask)
{
    int b = blockIdx.x, k = threadIdx.x;
    const float INF = __int_as_float(0x7f800000);

    float s0 = obj[(b * KQ + k) * 2];
    float s1 = obj[(b * KQ + k) * 2 + 1];
    float objn = 1.f / (1.f + expf(s0 - s1));
    bool om = objn > 0.75f;

    float dx = center[b * 3 + 0] - xyz[(b * KQ + k) * 3 + 0];
    float dy = center[b * 3 + 1] - xyz[(b * KQ + k) * 3 + 1];
    float dz = center[b * 3 + 2] - xyz[(b * KQ + k) * 3 + 2];
    float dist = sqrtf(dx * dx + dy * dy + dz * dz);
    float d = om ? dist : INF;

    __shared__ float ds[KQ];
    ds[k] = d;
    __syncthreads();
    for (int sz = 2; sz <= KQ; sz <<= 1) {
        for (int j = sz >> 1; j > 0; j >>= 1) {
            int ixj = k ^ j;
            if (ixj > k) {
                bool up = ((k & sz) == 0);
                float a = ds[k], bb = ds[ixj];
                if ((a > bb) == up) { ds[k] = bb; ds[ixj] = a; }
            }
            __syncthreads();
        }
    }
    float maxd = ds[15];
    bool msk = om && (d <= maxd);
    g_mask[b * KQ + k] = msk ? 1 : 0;
    out_mask[b * KQ + k] = msk ? 1.f : 0.f;
}

// ------------------------- init kernel ---------------------------------------
__global__ void init_kernel(const float* __restrict__ enc,
                            const float* __restrict__ ref_obj)
{
    int b = blockIdx.x, tid = threadIdx.x;  // 384 threads
    if (tid < VDQ) {
        float s = 0.f;
        const float* eb = enc + (size_t)b * KQ * VDQ;
        #pragma unroll 4
        for (int k = 0; k < KQ; k++) s += eb[k * VDQ + tid];
        g_init[b * (VDQ + ODQ) + tid] = s * (1.f / (float)KQ);
    } else {
        int j = tid - VDQ;
        float v = ref_obj[b * ODQ + j];
        g_init[b * (VDQ + ODQ) + VDQ + j] = v;
        g_x[b * XDIM + EQ + VDQ + j] = v;   // constant across timesteps
    }
}

// ------------------------- init h0/c0 fused GEMM -----------------------------
__global__ void init_hc(const float* __restrict__ Wh, const float* __restrict__ bh,
                        const float* __restrict__ Wc, const float* __restrict__ bc)
{
    const int K = VDQ + ODQ;   // 384
    __shared__ float As[16 * 32];
    __shared__ float Bs[16 * 64];
    int tid = threadIdx.x;
    int m0 = blockIdx.y * 32;
    int n0 = blockIdx.x * 64;
    const float* Bp; const float* bias; float* out; int col;
    if (n0 < 512) { Bp = Wh; bias = bh; out = g_h; col = n0; }
    else          { Bp = Wc; bias = bc; out = g_c; col = n0 - 512; }

    int tx = tid & 15, ty = tid >> 4;
    ull acc[2][2] = {{0ull, 0ull}, {0ull, 0ull}};

    for (int k0 = 0; k0 < K; k0 += 16) {
        if (tid < 128) {
            int m = tid >> 2, kq = (tid & 3) * 4;
            float4 v = *(const float4*)&g_init[(m0 + m) * K + k0 + kq];
            As[(kq + 0) * 32 + m] = v.x; As[(kq + 1) * 32 + m] = v.y;
            As[(kq + 2) * 32 + m] = v.z; As[(kq + 3) * 32 + m] = v.w;
        }
        {
            int n = tid >> 2, kq = (tid & 3) * 4;
            float4 v = *(const float4*)&Bp[(size_t)(col + n) * K + k0 + kq];
            Bs[(kq + 0) * 64 + n] = v.x; Bs[(kq + 1) * 64 + n] = v.y;
            Bs[(kq + 2) * 64 + n] = v.z; Bs[(kq + 3) * 64 + n] = v.w;
        }
        __syncthreads();
        #pragma unroll
        for (int kk = 0; kk < 16; kk++) {
            float2 a = *(const float2*)&As[kk * 32 + ty * 2];
            ull a0 = pk2(a.x, a.x), a1 = pk2(a.y, a.y);
            const ull* bp = (const ull*)&Bs[kk * 64 + tx * 4];
            ull b01 = bp[0], b23 = bp[1];
            fma2(acc[0][0], a0, b01); fma2(acc[0][1], a0, b23);
            fma2(acc[1][0], a1, b01); fma2(acc[1][1], a1, b23);
        }
        __syncthreads();
    }
    #pragma unroll
    for (int i = 0; i < 2; i++) {
        int m = m0 + ty * 2 + i;
        int nb = col + tx * 4;
        float* cr = out + m * DQ + nb;
        cr[0] = lo32(acc[i][0]) + bias[nb + 0];
        cr[1] = hi32(acc[i][0]) + bias[nb + 1];
        cr[2] = lo32(acc[i][1]) + bias[nb + 2];
        cr[3] = hi32(acc[i][1]) + bias[nb + 3];
    }
}

// ------------------------- noop (ncu launch-position shim) -------------------
__global__ void noop_kernel() {}

// ------------------------- persistent decoder loop ---------------------------
// grid 256 x 256 threads. Phases per step:
//   A1 (blocks 0..39):  Yp[s] partial = h @ [Wd;Wf]^T, split-K 4, 64x128 tiles
//   bar
//   B (0..127) attention  ||  A2 (128..255): Yp hh columns, split-K 4
//   bar
//   C (0..63): gates = x @ Wih^T (gate-interleaved 64x64 tiles) + LSTM epilogue
//   bar
__global__ void __launch_bounds__(256, 2)
decoder_loop(const float* __restrict__ enc,
             const float* __restrict__ Wd, const float* __restrict__ Wf,
             const float* __restrict__ Whh,
             const float* __restrict__ b_dec, const float* __restrict__ b_fbeta,
             const float* __restrict__ w_full, const float* __restrict__ b_full,
             const float* __restrict__ Wih, const float* __restrict__ b_ih,
             const float* __restrict__ b_hh,
             const float* __restrict__ emb_table, const float* __restrict__ init_emb,
             const int* __restrict__ lang_idx, const int* __restrict__ lang_len,
             float* __restrict__ out_alpha)
{
    __shared__ float pool[3072];            // 12 KB
    float* As = pool;                       // [16][64]
    float* Bs = pool + 1024;                // [16][128]
    int tid = threadIdx.x, bid = blockIdx.x;
    int tx = tid & 15, ty = tid >> 4;       // 16x16 thread grid
    int la_m = tid >> 2, la_k = (tid & 3) * 4;   // A loader: 64 rows x 16 k
    unsigned round = 0;

    for (int t = 0; t < TQ; t++) {
        // ================= Phase A1: Yp cols [0,640) =================
        if (bid < 40) {
            int s  = bid & 3;
            int mt = (bid >> 2) & 1;
            int nt = bid >> 3;               // 0..4
            int m0 = mt * 64, n0 = nt * 128, k0 = s * 128;
            const float* Bg = (n0 < 512) ? (Wd + (size_t)n0 * DQ)
                                         : (Wf + (size_t)(n0 - 512) * DQ);
            float* Cp = g_Yp + (size_t)s * BQ * YDIM + n0;

            ull acc[4][4];
            #pragma unroll
            for (int i = 0; i < 4; i++)
                #pragma unroll
                for (int p = 0; p < 4; p++) acc[i][p] = 0ull;

            for (int kt = 0; kt < 8; kt++) {
                int k = k0 + kt * 16;
                {
                    float4 v = __ldcg((const float4*)&g_h[(m0 + la_m) * DQ + k + la_k]);
                    As[(la_k + 0) * 64 + la_m] = v.x; As[(la_k + 1) * 64 + la_m] = v.y;
                    As[(la_k + 2) * 64 + la_m] = v.z; As[(la_k + 3) * 64 + la_m] = v.w;
                }
                #pragma unroll
                for (int h = 0; h < 2; h++) {
                    int n = la_m + h * 64;
                    float4 v = __ldg((const float4*)&Bg[(size_t)n * DQ + k + la_k]);
                    Bs[(la_k + 0) * 128 + n] = v.x; Bs[(la_k + 1) * 128 + n] = v.y;
                    Bs[(la_k + 2) * 128 + n] = v.z; Bs[(la_k + 3) * 128 + n] = v.w;
                }
                __syncthreads();
                #pragma unroll
                for (int kk = 0; kk < 16; kk++) {
                    float4 av = *(const float4*)&As[kk * 64 + ty * 4];
                    ull pa0 = pk2(av.x, av.x), pa1 = pk2(av.y, av.y);
                    ull pa2 = pk2(av.z, av.z), pa3 = pk2(av.w, av.w);
                    const ull* bp = (const ull*)&Bs[kk * 128 + tx * 8];
                    ull b0 = bp[0], b1 = bp[1], b2 = bp[2], b3 = bp[3];
                    fma2(acc[0][0], pa0, b0); fma2(acc[0][1], pa0, b1); fma2(acc[0][2], pa0, b2); fma2(acc[0][3], pa0, b3);
                    fma2(acc[1][0], pa1, b0); fma2(acc[1][1], pa1, b1); fma2(acc[1][2], pa1, b2); fma2(acc[1][3], pa1, b3);
                    fma2(acc[2][0], pa2, b0); fma2(acc[2][1], pa2, b1); fma2(acc[2][2], pa2, b2); fma2(acc[2][3], pa2, b3);
                    fma2(acc[3][0], pa3, b0); fma2(acc[3][1], pa3, b1); fma2(acc[3][2], pa3, b2); fma2(acc[3][3], pa3, b3);
                }
                __syncthreads();
            }
            #pragma unroll
            for (int i = 0; i < 4; i++) {
                int m = m0 + ty * 4 + i;
                float4 o0 = make_float4(lo32(acc[i][0]), hi32(acc[i][0]),
                                        lo32(acc[i][1]), hi32(acc[i][1]));
                float4 o1 = make_float4(lo32(acc[i][2]), hi32(acc[i][2]),
                                        lo32(acc[i][3]), hi32(acc[i][3]));
                __stcg((float4*)&Cp[(size_t)m * YDIM + tx * 8], o0);
                __stcg((float4*)&Cp[(size_t)m * YDIM + tx * 8 + 4], o1);
            }
        }
        grid_bar((++round) * GRID_P);

        // ========== Phase B (blocks 0..127) || A2 (blocks 128..255) ==========
        if (bid >= 128) {
            // A2: Yp cols [640, 2688) = h @ Whh^T, split-K 4
            int idx = bid - 128;
            int s  = idx & 3;
            int mt = (idx >> 2) & 1;
            int nt = idx >> 3;               // 0..15
            int m0 = mt * 64, n0 = nt * 128, k0 = s * 128;
            const float* Bg = Whh + (size_t)n0 * DQ;
            float* Cp = g_Yp + (size_t)s * BQ * YDIM + 640 + n0;

            ull acc[4][4];
            #pragma unroll
            for (int i = 0; i < 4; i++)
                #pragma unroll
                for (int p = 0; p < 4; p++) acc[i][p] = 0ull;

            for (int kt = 0; kt < 8; kt++) {
                int k = k0 + kt * 16;
                {
                    float4 v = __ldcg((const float4*)&g_h[(m0 + la_m) * DQ + k + la_k]);
                    As[(la_k + 0) * 64 + la_m] = v.x; As[(la_k + 1) * 64 + la_m] = v.y;
                    As[(la_k + 2) * 64 + la_m] = v.z; As[(la_k + 3) * 64 + la_m] = v.w;
                }
                #pragma unroll
                for (int h = 0; h < 2; h++) {
                    int n = la_m + h * 64;
                    float4 v = __ldg((const float4*)&Bg[(size_t)n * DQ + k + la_k]);
                    Bs[(la_k + 0) * 128 + n] = v.x; Bs[(la_k + 1) * 128 + n] = v.y;
                    Bs[(la_k + 2) * 128 + n] = v.z; Bs[(la_k + 3) * 128 + n] = v.w;
                }
                __syncthreads();
                #pragma unroll
                for (int kk = 0; kk < 16; kk++) {
                    float4 av = *(const float4*)&As[kk * 64 + ty * 4];
                    ull pa0 = pk2(av.x, av.x), pa1 = pk2(av.y, av.y);
                    ull pa2 = pk2(av.z, av.z), pa3 = pk2(av.w, av.w);
                    const ull* bp = (const ull*)&Bs[kk * 128 + tx * 8];
                    ull b0 = bp[0], b1 = bp[1], b2 = bp[2], b3 = bp[3];
                    fma2(acc[0][0], pa0, b0); fma2(acc[0][1], pa0, b1); fma2(acc[0][2], pa0, b2); fma2(acc[0][3], pa0, b3);
                    fma2(acc[1][0], pa1, b0); fma2(acc[1][1], pa1, b1); fma2(acc[1][2], pa1, b2); fma2(acc[1][3], pa1, b3);
                    fma2(acc[2][0], pa2, b0); fma2(acc[2][1], pa2, b1); fma2(acc[2][2], pa2, b2); fma2(acc[2][3], pa2, b3);
                    fma2(acc[3][0], pa3, b0); fma2(acc[3][1], pa3, b1); fma2(acc[3][2], pa3, b2); fma2(acc[3][3], pa3, b3);
                }
                __syncthreads();
            }
            #pragma unroll
            for (int i = 0; i < 4; i++) {
                int m = m0 + ty * 4 + i;
                float4 o0 = make_float4(lo32(acc[i][0]), hi32(acc[i][0]),
                                        lo32(acc[i][1]), hi32(acc[i][1]));
                float4 o1 = make_float4(lo32(acc[i][2]), hi32(acc[i][2]),
                                        lo32(acc[i][3]), hi32(acc[i][3]));
                __stcg((float4*)&Cp[(size_t)m * YDIM + tx * 8], o0);
                __stcg((float4*)&Cp[(size_t)m * YDIM + tx * 8 + 4], o1);
            }
        } else {
            // B: attention for batch b = bid
            int b = bid;
            float* att2_s  = pool;          // 512
            float* w_s     = pool + 512;    // 512
            float* att_s   = pool + 1024;   // 128
            float* red     = pool + 1152;   // 128
            float* alpha_s = pool + 1280;   // 128
            float* part    = pool + 1408;   // 256

            #pragma unroll
            for (int a = tid; a < AQ; a += 256) {
                float v = b_dec[a];
                #pragma unroll
                for (int s = 0; s < NSPLIT; s++)
                    v += __ldcg(&g_Yp[((size_t)s * BQ + b) * YDIM + a]);
                att2_s[a] = v;
                w_s[a] = w_full[a];
            }
            __syncthreads();

            int warp = tid >> 5, lane = tid & 31;
            for (int k = warp; k < KQ; k += 8) {
                const float* a1 = g_att1 + ((size_t)b * KQ + k) * AQ;
                float s = 0.f;
                #pragma unroll
                for (int c = 0; c < 4; c++) {
                    int base = c * 128 + lane * 4;
                    float4 v = __ldg((const float4*)&a1[base]);
                    s += fmaxf(v.x + att2_s[base + 0], 0.f) * w_s[base + 0];
                    s += fmaxf(v.y + att2_s[base + 1], 0.f) * w_s[base + 1];
                    s += fmaxf(v.z + att2_s[base + 2], 0.f) * w_s[base + 2];
                    s += fmaxf(v.w + att2_s[base + 3], 0.f) * w_s[base + 3];
                }
                #pragma unroll
                for (int o = 16; o; o >>= 1) s += __shfl_down_sync(0xffffffffu, s, o);
                if (lane == 0) att_s[k] = s + b_full[0];
            }
            __syncthreads();

            if (tid < KQ)
                red[tid] = g_mask[b * KQ + tid] ? att_s[tid]
                                                : -__int_as_float(0x7f800000);
            __syncthreads();
            for (int s = 64; s > 0; s >>= 1) {
                if (tid < s) red[tid] = fmaxf(red[tid], red[tid + s]);
                __syncthreads();
            }
            float mx = red[0];
            if (isinf(mx)) mx = 0.f;
            __syncthreads();
            if (tid < KQ) {
                float e = g_mask[b * KQ + tid] ? expf(att_s[tid] - mx) : 0.f;
                alpha_s[tid] = e;
                red[tid] = e;
            }
            __syncthreads();
            for (int s = 64; s > 0; s >>= 1) {
                if (tid < s) red[tid] += red[tid + s];
                __syncthreads();
            }
            float dsum = red[0];
            float inv = (dsum > 0.f) ? 1.f / fmaxf(dsum, 1e-30f) : 0.f;
            __syncthreads();
            if (tid < KQ) alpha_s[tid] *= inv;
            __syncthreads();

            {
                int v = tid & (VDQ - 1), q = tid >> 7;   // q 0..1
                const float* eb = enc + (size_t)b * KQ * VDQ;
                float s = 0.f;
                #pragma unroll 4
                for (int k = q * 64; k < q * 64 + 64; k++)
                    s += alpha_s[k] * __ldg(&eb[k * VDQ + v]);
                part[tid] = s;
            }
            __syncthreads();

            bool active = (t < lang_len[b]);
            if (tid < VDQ) {
                float aw = part[tid] + part[tid + 128];
                float gv = b_fbeta[tid];
                #pragma unroll
                for (int s = 0; s < NSPLIT; s++)
                    gv += __ldcg(&g_Yp[((size_t)s * BQ + b) * YDIM + 512 + tid]);
                __stcg(&g_x[b * XDIM + EQ + tid], aw * sigf(gv));
                out_alpha[(size_t)b * TQ * KQ + (size_t)t * KQ + tid]
                    = active ? alpha_s[tid] : 0.f;
            }
            for (int e = tid; e < EQ; e += 256) {
                float em = (t == 0) ? init_emb[e]
                         : emb_table[(size_t)lang_idx[b * TQ + (t - 1)] * EQ + e];
                __stcg(&g_x[b * XDIM + e], em);
            }
        }
        grid_bar((++round) * GRID_P);

        // ================= Phase C: gates GEMM + LSTM =================
        if (bid < 64) {
            int mt = bid & 1, jt = bid >> 1;    // 32 j-tiles of 16
            int m0 = mt * 64, j0 = jt * 16;
            // Bs cols (64): col = jl*4 + seg; weight row = seg*512 + j0 + jl
            int c_col = tid >> 2, c_k = (tid & 3) * 4;
            int c_row = (c_col & 3) * 512 + j0 + (c_col >> 2);
            const float* Brow = Wih + (size_t)c_row * XDIM;

            ull acc[4][2];
            #pragma unroll
            for (int i = 0; i < 4; i++) { acc[i][0] = 0ull; acc[i][1] = 0ull; }

            for (int kt = 0; kt < 43; kt++) {
                int k = kt * 16;
                {
                    float4 v = ld4g_cg(&g_x[(m0 + la_m) * XDIM], k + la_k, XDIM);
                    As[(la_k + 0) * 64 + la_m] = v.x; As[(la_k + 1) * 64 + la_m] = v.y;
                    As[(la_k + 2) * 64 + la_m] = v.z; As[(la_k + 3) * 64 + la_m] = v.w;
                }
                {
                    float4 v = ld4g_ro(Brow, k + c_k, XDIM);
                    Bs[(c_k + 0) * 64 + c_col] = v.x; Bs[(c_k + 1) * 64 + c_col] = v.y;
                    Bs[(c_k + 2) * 64 + c_col] = v.z; Bs[(c_k + 3) * 64 + c_col] = v.w;
                }
                __syncthreads();
                #pragma unroll
                for (int kk = 0; kk < 16; kk++) {
                    float4 av = *(const float4*)&As[kk * 64 + ty * 4];
                    const ull* bp = (const ull*)&Bs[kk * 64 + tx * 4];
                    ull b0 = bp[0], b1 = bp[1];
                    ull pa0 = pk2(av.x, av.x), pa1 = pk2(av.y, av.y);
                    ull pa2 = pk2(av.z, av.z), pa3 = pk2(av.w, av.w);
                    fma2(acc[0][0], pa0, b0); fma2(acc[0][1], pa0, b1);
                    fma2(acc[1][0], pa1, b0); fma2(acc[1][1], pa1, b1);
                    fma2(acc[2][0], pa2, b0); fma2(acc[2][1], pa2, b1);
                    fma2(acc[3][0], pa3, b0); fma2(acc[3][1], pa3, b1);
                }
                __syncthreads();
            }

            int j = j0 + tx;
            float bi_i = b_ih[j]        + b_hh[j];
            float bi_f = b_ih[512 + j]  + b_hh[512 + j];
            float bi_g = b_ih[1024 + j] + b_hh[1024 + j];
            float bi_o = b_ih[1536 + j] + b_hh[1536 + j];
            #pragma unroll
            for (int i = 0; i < 4; i++) {
                int b = m0 + ty * 4 + i;
                float gi = lo32(acc[i][0]) + bi_i;
                float gf = hi32(acc[i][0]) + bi_f;
                float gg = lo32(acc[i][1]) + bi_g;
                float go = hi32(acc[i][1]) + bi_o;
                #pragma unroll
                for (int s = 0; s < NSPLIT; s++) {
                    const float* Yb = g_Yp + ((size_t)s * BQ + b) * YDIM + 640;
                    gi += __ldcg(&Yb[j]);
                    gf += __ldcg(&Yb[512 + j]);
                    gg += __ldcg(&Yb[1024 + j]);
                    go += __ldcg(&Yb[1536 + j]);
                }
                float c_old = __ldcg(&g_c[b * DQ + j]);
                float cn = sigf(gf) * c_old + sigf(gi) * tanhf(gg);
                float hn = sigf(go) * tanhf(cn);
                bool act = t < lang_len[b];
                float h_prev = __ldcg(&g_h[b * DQ + j]);
                float h_out = act ? hn : h_prev;
                if (act) {
                    __stcg(&g_c[b * DQ + j], cn);
                    __stcg(&g_h[b * DQ + j], hn);
                }
                g_hstore[((size_t)t * BQ + b) * DQ + j] = h_out;
            }
        }
        if (t != TQ - 1) grid_bar((++round) * GRID_P);
    }

    // done protocol: reset barrier counters for next graph replay
    __syncthreads();
    __threadfence();
    if (tid == 0) {
        asm volatile("red.release.gpu.global.add.u32 [%0], %1;"
                     :: "l"(&g_done), "r"(1u) : "memory");
        if (bid == 0) {
            unsigned v;
            do {
                asm volatile("ld.acquire.gpu.global.u32 %0, [%1];"
                             : "=r"(v) : "l"(&g_done) : "memory");
            } while (v < (unsigned)GRID_P);
            asm volatile("st.global.cg.u32 [%0], %1;" :: "l"(&g_bar), "r"(0u) : "memory");
            __threadfence();
            asm volatile("st.release.gpu.global.u32 [%0], %1;"
                         :: "l"(&g_done), "r"(0u) : "memory");
        }
    }
}

// ------------------------- big GEMM (att1, fc) --------------------------------
__global__ void gemm_big(const float* __restrict__ A, const float* __restrict__ B,
                         const float* __restrict__ bias, float* __restrict__ C,
                         int M, int N, int K, int ldc,
                         const int* __restrict__ lang_len)
{
    const int BK = 16;
    __shared__ float As[BK][64];
    __shared__ float Bs[BK][128];
    int tid = threadIdx.x;
    int m0 = blockIdx.y * 64, n0 = blockIdx.x * 128;
    int tx = tid & 15, ty = tid >> 4;
    ull acc[4][4];
    #pragma unroll
    for (int i = 0; i < 4; i++)
        #pragma unroll
        for (int p = 0; p < 4; p++) acc[i][p] = 0ull;

    for (int k0 = 0; k0 < K; k0 += BK) {
        {
            int m = tid >> 2, kq = (tid & 3) * 4;
            float4 v = *(const float4*)&A[(size_t)(m0 + m) * K + k0 + kq];
            As[kq + 0][m] = v.x; As[kq + 1][m] = v.y; As[kq + 2][m] = v.z; As[kq + 3][m] = v.w;
        }
        #pragma unroll
        for (int rr = 0; rr < 2; rr++) {
            int r = tid + rr * 256;
            int n = r >> 2, kq = (r & 3) * 4;
            int nn = n0 + n;
            float4 v = make_float4(0.f, 0.f, 0.f, 0.f);
            if (nn < N) v = *(const float4*)&B[(size_t)nn * K + k0 + kq];
            Bs[kq + 0][n] = v.x; Bs[kq + 1][n] = v.y; Bs[kq + 2][n] = v.z; Bs[kq + 3][n] = v.w;
        }
        __syncthreads();
        #pragma unroll
        for (int kk = 0; kk < BK; kk++) {
            float4 av = *(const float4*)&As[kk][ty * 4];
            ull pa0 = pk2(av.x, av.x), pa1 = pk2(av.y, av.y);
            ull pa2 = pk2(av.z, av.z), pa3 = pk2(av.w, av.w);
            const ull* bp = (const ull*)&Bs[kk][tx * 8];
            ull b0 = bp[0], b1 = bp[1], b2 = bp[2], b3 = bp[3];
            fma2(acc[0][0], pa0, b0); fma2(acc[0][1], pa0, b1); fma2(acc[0][2], pa0, b2); fma2(acc[0][3], pa0, b3);
            fma2(acc[1][0], pa1, b0); fma2(acc[1][1], pa1, b1); fma2(acc[1][2], pa1, b2); fma2(acc[1][3], pa1, b3);
            fma2(acc[2][0], pa2, b0); fma2(acc[2][1], pa2, b1); fma2(acc[2][2], pa2, b2); fma2(acc[2][3], pa2, b3);
            fma2(acc[3][0], pa3, b0); fma2(acc[3][1], pa3, b1); fma2(acc[3][2], pa3, b2); fma2(acc[3][3], pa3, b3);
        }
        __syncthreads();
    }

    #pragma unroll
    for (int i = 0; i < 4; i++) {
        int m = m0 + ty * 4 + i;
        bool zero = (lang_len != nullptr) && ((m >> 7) >= lang_len[m & 127]);
        float* cr = C + (size_t)m * ldc;
        #pragma unroll
        for (int p = 0; p < 4; p++) {
            int nn = n0 + tx * 8 + p * 2;
            if (nn < N) {
                float v = lo32(acc[i][p]) + bias[nn];
                cr[nn] = zero ? 0.f : v;
            }
            if (nn + 1 < N) {
                float v = hi32(acc[i][p]) + bias[nn + 1];
                cr[nn + 1] = zero ? 0.f : v;
            }
        }
    }
}

// ------------------------- final transpose [T,B,V] -> [B,V,T] ----------------
__global__ void transpose_preds(float* __restrict__ out)
{
    __shared__ float tile[32][33];
    int b = blockIdx.x;
    int v0 = blockIdx.y * 32;
    int tx = threadIdx.x, ty = threadIdx.y;
    tile[ty][tx] = g_predsT[(size_t)ty * BQ * VQ + (size_t)b * VQ + v0 + tx];
    __syncthreads();
    out[(size_t)b * VQ * TQ + (size_t)(v0 + ty) * TQ + tx] = tile[tx][ty];
}

// ------------------------- launch ---------------------------------------------
extern "C" void kernel_launch(void* const* d_in, const int* in_sizes, int n_in,
                              void* d_out, int out_size)
{
    const float* enc       = (const float*)d_in[0];
    const float* ref_obj   = (const float*)d_in[1];
    const float* obj_sc    = (const float*)d_in[2];
    const float* center    = (const float*)d_in[3];
    const float* xyz       = (const float*)d_in[4];
    const int*   lang_idx  = (const int*)d_in[5];
    const int*   lang_len  = (const int*)d_in[6];
    const float* emb_tab   = (const float*)d_in[7];
    const float* init_emb  = (const float*)d_in[8];
    const float* W_enc_att = (const float*)d_in[9];
    const float* b_enc_att = (const float*)d_in[10];
    const float* W_dec_att = (const float*)d_in[11];
    const float* b_dec_att = (const float*)d_in[12];
    const float* w_full    = (const float*)d_in[13];
    const float* b_full    = (const float*)d_in[14];
    const float* W_ih      = (const float*)d_in[15];
    const float* b_ih      = (const float*)d_in[16];
    const float* W_hh      = (const float*)d_in[17];
    const float* b_hh      = (const float*)d_in[18];
    const float* W_init_h  = (const float*)d_in[19];
    const float* b_init_h  = (const float*)d_in[20];
    const float* W_init_c  = (const float*)d_in[21];
    const float* b_init_c  = (const float*)d_in[22];
    const float* W_fbeta   = (const float*)d_in[23];
    const float* b_fbeta   = (const float*)d_in[24];
    const float* W_fc      = (const float*)d_in[25];
    const float* b_fc      = (const float*)d_in[26];

    float* out       = (float*)d_out;
    float* out_alpha = out + (size_t)BQ * VQ * TQ;
    float* out_mask  = out_alpha + (size_t)BQ * TQ * KQ;

    float *p_att1, *p_hstore, *p_predsT;
    cudaGetSymbolAddress((void**)&p_att1,   g_att1);
    cudaGetSymbolAddress((void**)&p_hstore, g_hstore);
    cudaGetSymbolAddress((void**)&p_predsT, g_predsT);

    // precompute
    mask_kernel<<<BQ, KQ>>>(obj_sc, center, xyz, out_mask);                 // 1
    init_kernel<<<BQ, VDQ + ODQ>>>(enc, ref_obj);                           // 2
    init_hc<<<dim3(16, 4), 256>>>(W_init_h, b_init_h, W_init_c, b_init_c);  // 3
    gemm_big<<<dim3(4, 256), 256>>>(enc, W_enc_att, b_enc_att, p_att1,      // 4
                                    BQ * KQ, AQ, VDQ, AQ, nullptr);
    noop_kernel<<<1, 1>>>();                                                // 5 (ncu shim)

    // the whole 32-step recurrence in one persistent kernel                // 6
    decoder_loop<<<GRID_P, 256>>>(enc, W_dec_att, W_fbeta, W_hh,
                                  b_dec_att, b_fbeta, w_full, b_full,
                                  W_ih, b_ih, b_hh, emb_tab, init_emb,
                                  lang_idx, lang_len, out_alpha);

    // one big fc: preds[T*B, V] = hstore @ W_fc^T + b_fc                    // 7
    gemm_big<<<dim3((VQ + 127) / 128, (TQ * BQ) / 64), 256>>>(
        p_hstore, W_fc, b_fc, p_predsT, TQ * BQ, VQ, DQ, VQ, lang_len);

    // [T,B,V] -> [B,V,T]                                                    // 8
    transpose_preds<<<dim3(BQ, VQ / 32), dim3(32, 32)>>>(out);
}

// round 7
// speedup vs baseline: 1.4854x; 1.4854x over previous
#include <cuda_runtime.h>
#include <math.h>
#include <stdint.h>

#define BQ 128
#define KQ 128
#define VDQ 128
#define ODQ 256
#define EQ 300
#define AQ 512
#define DQ 512
#define VQ 4000
#define TQ 32
#define XDIM 684
#define YDIM 2688    // 512 dec | 128 fbeta | 2048 hh
#define GN 2048      // 4*DQ gate width
#define GRID_P 256
#define NSPLIT 4

// ------------------------- scratch (device globals) -------------------------
__device__ float g_att1[(size_t)BQ * KQ * AQ];           // 32 MB
__device__ float g_Yp[(size_t)NSPLIT * BQ * YDIM];       // 5.5 MB
__device__ float g_Yhh[BQ * GN];                         // 1 MB
__device__ float g_h[BQ * DQ];
__device__ float g_c[BQ * DQ];
__device__ float g_awe[BQ * VDQ];
__device__ float g_init[BQ * (VDQ + ODQ)];
__device__ float g_Gv[(size_t)VQ * GN];                  // 32.8 MB
__device__ float g_Gref[BQ * GN];                        // 1 MB
__device__ float g_Ginit[GN];
__device__ float g_hstore[(size_t)TQ * BQ * DQ];         // 8 MB
__device__ float g_predsT[(size_t)TQ * BQ * VQ];         // 64 MB
__device__ unsigned char g_mask[BQ * KQ];
__device__ unsigned g_bar = 0;
__device__ unsigned g_done = 0;

typedef unsigned long long ull;
__device__ __forceinline__ ull pk2(float x, float y) {
    ull r; asm("mov.b64 %0,{%1,%2};" : "=l"(r) : "f"(x), "f"(y)); return r;
}
__device__ __forceinline__ void fma2(ull& d, ull a, ull b) {
    asm("fma.rn.f32x2 %0,%1,%2,%0;" : "+l"(d) : "l"(a), "l"(b));
}
__device__ __forceinline__ float lo32(ull v) { return __uint_as_float((unsigned)v); }
__device__ __forceinline__ float hi32(ull v) { return __uint_as_float((unsigned)(v >> 32)); }
__device__ __forceinline__ float sigf(float x) { return 1.f / (1.f + expf(-x)); }

// CG-style grid barrier: bar.sync ; t0 release-arrive ; t0 acquire-spin ; bar.sync
__device__ __forceinline__ void grid_bar(unsigned target)
{
    __syncthreads();
    if (threadIdx.x == 0) {
        asm volatile("red.release.gpu.global.add.u32 [%0], %1;"
                     :: "l"(&g_bar), "r"(1u) : "memory");
        unsigned v;
        do {
            asm volatile("ld.acquire.gpu.global.u32 %0, [%1];"
                         : "=r"(v) : "l"(&g_bar) : "memory");
        } while (v < target);
    }
    __syncthreads();
}

__device__ __forceinline__ float4 ld4g_ro(const float* base, int k, int limit) {
    if (k + 4 <= limit) return __ldg((const float4*)(base + k));
    float4 v = make_float4(0.f, 0.f, 0.f, 0.f);
    if (k + 0 < limit) v.x = __ldg(base + k + 0);
    if (k + 1 < limit) v.y = __ldg(base + k + 1);
    if (k + 2 < limit) v.z = __ldg(base + k + 2);
    if (k + 3 < limit) v.w = __ldg(base + k + 3);
    return v;
}

// ---------------- fused precompute: mask | init | Ginit ----------------------
__global__ void fused_pre(const float* __restrict__ obj,
                          const float* __restrict__ center,
                          const float* __restrict__ xyz,
                          const float* __restrict__ enc,
                          const float* __restrict__ ref_obj,
                          const float* __restrict__ init_emb,
                          const float* __restrict__ Wih,
                          float* __restrict__ out_mask)
{
    int bid = blockIdx.x, tid = threadIdx.x;   // 256 threads
    if (bid < 128) {
        // ---- object mask for batch b = bid (threads 0..127 active) ----
        __shared__ float ds[KQ];
        __shared__ float dk[KQ];
        int b = bid, k = tid;
        const float INF = __int_as_float(0x7f800000);
        float d = INF; bool om = false;
        if (k < KQ) {
            float s0 = obj[(b * KQ + k) * 2];
            float s1 = obj[(b * KQ + k) * 2 + 1];
            om = (1.f / (1.f + expf(s0 - s1))) > 0.75f;
            float dx = center[b * 3 + 0] - xyz[(b * KQ + k) * 3 + 0];
            float dy = center[b * 3 + 1] - xyz[(b * KQ + k) * 3 + 1];
            float dz = center[b * 3 + 2] - xyz[(b * KQ + k) * 3 + 2];
            float dist = sqrtf(dx * dx + dy * dy + dz * dz);
            d = om ? dist : INF;
            ds[k] = d; dk[k] = d;
        }
        __syncthreads();
        for (int sz = 2; sz <= KQ; sz <<= 1) {
            for (int j = sz >> 1; j > 0; j >>= 1) {
                if (k < KQ) {
                    int ixj = k ^ j;
                    if (ixj > k) {
                        bool up = ((k & sz) == 0);
                        float a = ds[k], bb = ds[ixj];
                        if ((a > bb) == up) { ds[k] = bb; ds[ixj] = a; }
                    }
                }
                __syncthreads();
            }
        }
        if (k < KQ) {
            float maxd = ds[15];
            bool msk = om && (dk[k] <= maxd);
            g_mask[b * KQ + k] = msk ? 1 : 0;
            out_mask[b * KQ + k] = msk ? 1.f : 0.f;
        }
    } else if (bid < 256) {
        // ---- init vector for batch b = bid-128 ----
        int b = bid - 128;
        if (tid < VDQ) {
            float s = 0.f;
            const float* eb = enc + (size_t)b * KQ * VDQ;
            #pragma unroll 4
            for (int k = 0; k < KQ; k++) s += eb[k * VDQ + tid];
            g_init[b * (VDQ + ODQ) + tid] = s * (1.f / (float)KQ);
        }
        g_init[b * (VDQ + ODQ) + VDQ + tid] = ref_obj[b * ODQ + tid];
    } else {
        // ---- G_init[r] = sum_k init_emb[k] * Wih[r][k], r over 2048 ----
        int r = (bid - 256) * 256 + tid;
        const float* wr = Wih + (size_t)r * XDIM;
        float s = 0.f;
        #pragma unroll 4
        for (int k = 0; k < EQ; k++) s += init_emb[k] * wr[k];
        g_Ginit[r] = s;
    }
}

// ------------------------- init h0/c0 fused GEMM -----------------------------
__global__ void init_hc(const float* __restrict__ Wh, const float* __restrict__ bh,
                        const float* __restrict__ Wc, const float* __restrict__ bc)
{
    const int K = VDQ + ODQ;   // 384
    __shared__ float As[16 * 32];
    __shared__ float Bs[16 * 64];
    int tid = threadIdx.x;
    int m0 = blockIdx.y * 32;
    int n0 = blockIdx.x * 64;
    const float* Bp; const float* bias; float* out; int col;
    if (n0 < 512) { Bp = Wh; bias = bh; out = g_h; col = n0; }
    else          { Bp = Wc; bias = bc; out = g_c; col = n0 - 512; }

    int tx = tid & 15, ty = tid >> 4;
    ull acc[2][2] = {{0ull, 0ull}, {0ull, 0ull}};

    for (int k0 = 0; k0 < K; k0 += 16) {
        if (tid < 128) {
            int m = tid >> 2, kq = (tid & 3) * 4;
            float4 v = *(const float4*)&g_init[(m0 + m) * K + k0 + kq];
            As[(kq + 0) * 32 + m] = v.x; As[(kq + 1) * 32 + m] = v.y;
            As[(kq + 2) * 32 + m] = v.z; As[(kq + 3) * 32 + m] = v.w;
        }
        {
            int n = tid >> 2, kq = (tid & 3) * 4;
            float4 v = *(const float4*)&Bp[(size_t)(col + n) * K + k0 + kq];
            Bs[(kq + 0) * 64 + n] = v.x; Bs[(kq + 1) * 64 + n] = v.y;
            Bs[(kq + 2) * 64 + n] = v.z; Bs[(kq + 3) * 64 + n] = v.w;
        }
        __syncthreads();
        #pragma unroll
        for (int kk = 0; kk < 16; kk++) {
            float2 a = *(const float2*)&As[kk * 32 + ty * 2];
            ull a0 = pk2(a.x, a.x), a1 = pk2(a.y, a.y);
            const ull* bp = (const ull*)&Bs[kk * 64 + tx * 4];
            ull b01 = bp[0], b23 = bp[1];
            fma2(acc[0][0], a0, b01); fma2(acc[0][1], a0, b23);
            fma2(acc[1][0], a1, b01); fma2(acc[1][1], a1, b23);
        }
        __syncthreads();
    }
    #pragma unroll
    for (int i = 0; i < 2; i++) {
        int m = m0 + ty * 2 + i;
        int nb = col + tx * 4;
        float* cr = out + m * DQ + nb;
        cr[0] = lo32(acc[i][0]) + bias[nb + 0];
        cr[1] = hi32(acc[i][0]) + bias[nb + 1];
        cr[2] = lo32(acc[i][1]) + bias[nb + 2];
        cr[3] = hi32(acc[i][1]) + bias[nb + 3];
    }
}

// ------------- gemm128: C[M,N] = A[M,:K] @ B[N,:K]^T (+bias) -----------------
// 128x128 tile, 256 threads, 8x8 per thread, reg-prefetch pipeline.
// lang_len != null: zero row m when (m>>7) >= lang_len[m&127].
__global__ void __launch_bounds__(256)
gemm128(const float* __restrict__ A, int lda,
        const float* __restrict__ B, int ldb,
        const float* __restrict__ bias, float* __restrict__ C, int ldc,
        int M, int N, int K, const int* __restrict__ lang_len)
{
    __shared__ float As[16 * 128];
    __shared__ float Bs[16 * 128];
    int tid = threadIdx.x;
    int m0 = blockIdx.y * 128, n0 = blockIdx.x * 128;
    int lr = tid >> 1, lk = (tid & 1) * 8;
    int arow = m0 + lr; if (arow >= M) arow = M - 1;
    int brow = n0 + lr; if (brow >= N) brow = N - 1;
    const float* Ap = A + (size_t)arow * lda;
    const float* Bp = B + (size_t)brow * ldb;
    int tx = tid & 15, ty = tid >> 4;

    ull acc[8][4];
    #pragma unroll
    for (int i = 0; i < 8; i++)
        #pragma unroll
        for (int p = 0; p < 4; p++) acc[i][p] = 0ull;

    float4 ra0 = ld4g_ro(Ap, lk, K),     ra1 = ld4g_ro(Ap, lk + 4, K);
    float4 rb0 = ld4g_ro(Bp, lk, K),     rb1 = ld4g_ro(Bp, lk + 4, K);

    for (int k0 = 0; k0 < K; k0 += 16) {
        As[(lk + 0) * 128 + lr] = ra0.x; As[(lk + 1) * 128 + lr] = ra0.y;
        As[(lk + 2) * 128 + lr] = ra0.z; As[(lk + 3) * 128 + lr] = ra0.w;
        As[(lk + 4) * 128 + lr] = ra1.x; As[(lk + 5) * 128 + lr] = ra1.y;
        As[(lk + 6) * 128 + lr] = ra1.z; As[(lk + 7) * 128 + lr] = ra1.w;
        Bs[(lk + 0) * 128 + lr] = rb0.x; Bs[(lk + 1) * 128 + lr] = rb0.y;
        Bs[(lk + 2) * 128 + lr] = rb0.z; Bs[(lk + 3) * 128 + lr] = rb0.w;
        Bs[(lk + 4) * 128 + lr] = rb1.x; Bs[(lk + 5) * 128 + lr] = rb1.y;
        Bs[(lk + 6) * 128 + lr] = rb1.z; Bs[(lk + 7) * 128 + lr] = rb1.w;
        __syncthreads();
        int kn = k0 + 16;
        if (kn < K) {
            ra0 = ld4g_ro(Ap, kn + lk, K); ra1 = ld4g_ro(Ap, kn + lk + 4, K);
            rb0 = ld4g_ro(Bp, kn + lk, K); rb1 = ld4g_ro(Bp, kn + lk + 4, K);
        }
        #pragma unroll
        for (int kk = 0; kk < 16; kk++) {
            float4 a0 = *(const float4*)&As[kk * 128 + ty * 8];
            float4 a1 = *(const float4*)&As[kk * 128 + ty * 8 + 4];
            const ull* bp = (const ull*)&Bs[kk * 128 + tx * 8];
            ull b0 = bp[0], b1 = bp[1], b2 = bp[2], b3 = bp[3];
            ull pa;
            pa = pk2(a0.x, a0.x); fma2(acc[0][0], pa, b0); fma2(acc[0][1], pa, b1); fma2(acc[0][2], pa, b2); fma2(acc[0][3], pa, b3);
            pa = pk2(a0.y, a0.y); fma2(acc[1][0], pa, b0); fma2(acc[1][1], pa, b1); fma2(acc[1][2], pa, b2); fma2(acc[1][3], pa, b3);
            pa = pk2(a0.z, a0.z); fma2(acc[2][0], pa, b0); fma2(acc[2][1], pa, b1); fma2(acc[2][2], pa, b2); fma2(acc[2][3], pa, b3);
            pa = pk2(a0.w, a0.w); fma2(acc[3][0], pa, b0); fma2(acc[3][1], pa, b1); fma2(acc[3][2], pa, b2); fma2(acc[3][3], pa, b3);
            pa = pk2(a1.x, a1.x); fma2(acc[4][0], pa, b0); fma2(acc[4][1], pa, b1); fma2(acc[4][2], pa, b2); fma2(acc[4][3], pa, b3);
            pa = pk2(a1.y, a1.y); fma2(acc[5][0], pa, b0); fma2(acc[5][1], pa, b1); fma2(acc[5][2], pa, b2); fma2(acc[5][3], pa, b3);
            pa = pk2(a1.z, a1.z); fma2(acc[6][0], pa, b0); fma2(acc[6][1], pa, b1); fma2(acc[6][2], pa, b2); fma2(acc[6][3], pa, b3);
            pa = pk2(a1.w, a1.w); fma2(acc[7][0], pa, b0); fma2(acc[7][1], pa, b1); fma2(acc[7][2], pa, b2); fma2(acc[7][3], pa, b3);
        }
        __syncthreads();
    }

    #pragma unroll
    for (int i = 0; i < 8; i++) {
        int m = m0 + ty * 8 + i;
        if (m >= M) continue;
        bool zero = (lang_len != nullptr) && ((m >> 7) >= lang_len[m & 127]);
        float* cr = C + (size_t)m * ldc;
        #pragma unroll
        for (int p = 0; p < 4; p++) {
            int nn = n0 + tx * 8 + p * 2;
            if (nn < N) {
                float v = lo32(acc[i][p]) + (bias ? bias[nn] : 0.f);
                cr[nn] = zero ? 0.f : v;
            }
            if (nn + 1 < N) {
                float v = hi32(acc[i][p]) + (bias ? bias[nn + 1] : 0.f);
                cr[nn + 1] = zero ? 0.f : v;
            }
        }
    }
}

// ------------------------- persistent decoder loop ---------------------------
// P1 (168 blk): Yp[s] = h @ [Wd;Wf;Whh]^T partials (split-K 4, 64x128 tiles)
// P2: blocks 0..127 attention -> g_awe ; 128..255 reduce Yp hh -> g_Yhh
// P3 (32 blk): gates_awe = awe @ Wih[:,300:428]^T (virtual gate-interleaved),
//              + Gv(token) + Gref + Yhh + biases -> LSTM -> h,c,hstore
__global__ void __launch_bounds__(256, 2)
decoder_loop(const float* __restrict__ enc,
             const float* __restrict__ Wd, const float* __restrict__ Wf,
             const float* __restrict__ Whh,
             const float* __restrict__ b_dec, const float* __restrict__ b_fbeta,
             const float* __restrict__ w_full, const float* __restrict__ b_full,
             const float* __restrict__ Wih, const float* __restrict__ b_ih,
             const float* __restrict__ b_hh,
             const int* __restrict__ lang_idx, const int* __restrict__ lang_len,
             float* __restrict__ out_alpha)
{
    __shared__ float pool[3072];     // 12 KB
    float* As = pool;                // [16][64]
    float* Bs = pool + 1024;         // [16][128]
    int tid = threadIdx.x, bid = blockIdx.x;
    int tx = tid & 15, ty = tid >> 4;
    int ar = tid >> 1, ak = (tid & 1) * 8;   // loaders
    unsigned round = 0;

    // P1 B row pointer (per thread, fixed per tile)
    for (int t = 0; t < TQ; t++) {
        // ======================= P1 =======================
        if (bid < 168) {
            int s = bid & 3, tile = bid >> 2;
            int m0 = (tile & 1) * 64;
            int n0 = (tile >> 1) * 128;
            int k0 = s * 128;
            int n = n0 + ar;                    // ar = 0..127 (B loader row)
            const float* Brow;
            if (n < 512)      Brow = Wd  + (size_t)n * DQ;
            else if (n < 640) Brow = Wf  + (size_t)(n - 512) * DQ;
            else              Brow = Whh + (size_t)(n - 640) * DQ;

            ull acc[4][4];
            #pragma unroll
            for (int i = 0; i < 4; i++)
                #pragma unroll
                for (int p = 0; p < 4; p++) acc[i][p] = 0ull;

            for (int kt = 0; kt < 8; kt++) {
                int k = k0 + kt * 16;
                if (tid < 128) {
                    // A: 64 rows x 16 k ; thread: row tid>>1, k (tid&1)*8
                    int am = tid >> 1, akk = (tid & 1) * 8;
                    float4 v0 = __ldcg((const float4*)&g_h[(m0 + am) * DQ + k + akk]);
                    float4 v1 = __ldcg((const float4*)&g_h[(m0 + am) * DQ + k + akk + 4]);
                    As[(akk + 0) * 64 + am] = v0.x; As[(akk + 1) * 64 + am] = v0.y;
                    As[(akk + 2) * 64 + am] = v0.z; As[(akk + 3) * 64 + am] = v0.w;
                    As[(akk + 4) * 64 + am] = v1.x; As[(akk + 5) * 64 + am] = v1.y;
                    As[(akk + 6) * 64 + am] = v1.z; As[(akk + 7) * 64 + am] = v1.w;
                }
                {
                    float4 v0 = __ldg((const float4*)&Brow[k + ak]);
                    float4 v1 = __ldg((const float4*)&Brow[k + ak + 4]);
                    Bs[(ak + 0) * 128 + ar] = v0.x; Bs[(ak + 1) * 128 + ar] = v0.y;
                    Bs[(ak + 2) * 128 + ar] = v0.z; Bs[(ak + 3) * 128 + ar] = v0.w;
                    Bs[(ak + 4) * 128 + ar] = v1.x; Bs[(ak + 5) * 128 + ar] = v1.y;
                    Bs[(ak + 6) * 128 + ar] = v1.z; Bs[(ak + 7) * 128 + ar] = v1.w;
                }
                __syncthreads();
                #pragma unroll
                for (int kk = 0; kk < 16; kk++) {
                    float4 av = *(const float4*)&As[kk * 64 + ty * 4];
                    const ull* bp = (const ull*)&Bs[kk * 128 + tx * 8];
                    ull b0 = bp[0], b1 = bp[1], b2 = bp[2], b3 = bp[3];
                    ull pa;
                    pa = pk2(av.x, av.x); fma2(acc[0][0], pa, b0); fma2(acc[0][1], pa, b1); fma2(acc[0][2], pa, b2); fma2(acc[0][3], pa, b3);
                    pa = pk2(av.y, av.y); fma2(acc[1][0], pa, b0); fma2(acc[1][1], pa, b1); fma2(acc[1][2], pa, b2); fma2(acc[1][3], pa, b3);
                    pa = pk2(av.z, av.z); fma2(acc[2][0], pa, b0); fma2(acc[2][1], pa, b1); fma2(acc[2][2], pa, b2); fma2(acc[2][3], pa, b3);
                    pa = pk2(av.w, av.w); fma2(acc[3][0], pa, b0); fma2(acc[3][1], pa, b1); fma2(acc[3][2], pa, b2); fma2(acc[3][3], pa, b3);
                }
                __syncthreads();
            }
            float* Cp = g_Yp + (size_t)s * BQ * YDIM + n0;
            #pragma unroll
            for (int i = 0; i < 4; i++) {
                int m = m0 + ty * 4 + i;
                float4 o0 = make_float4(lo32(acc[i][0]), hi32(acc[i][0]),
                                        lo32(acc[i][1]), hi32(acc[i][1]));
                float4 o1 = make_float4(lo32(acc[i][2]), hi32(acc[i][2]),
                                        lo32(acc[i][3]), hi32(acc[i][3]));
                __stcg((float4*)&Cp[(size_t)m * YDIM + tx * 8], o0);
                __stcg((float4*)&Cp[(size_t)m * YDIM + tx * 8 + 4], o1);
            }
        }
        grid_bar((++round) * GRID_P);

        // ======================= P2 =======================
        if (bid < 128) {
            int b = bid;
            float* att2_s  = pool;
            float* w_s     = pool + 512;
            float* att_s   = pool + 1024;
            float* red     = pool + 1152;
            float* alpha_s = pool + 1280;
            float* part    = pool + 1408;    // 256

            #pragma unroll
            for (int a = tid; a < AQ; a += 256) {
                float v = b_dec[a];
                #pragma unroll
                for (int s = 0; s < NSPLIT; s++)
                    v += __ldcg(&g_Yp[((size_t)s * BQ + b) * YDIM + a]);
                att2_s[a] = v;
                w_s[a] = w_full[a];
            }
            __syncthreads();

            int warp = tid >> 5, lane = tid & 31;
            for (int k = warp; k < KQ; k += 8) {
                const float* a1 = g_att1 + ((size_t)b * KQ + k) * AQ;
                float s = 0.f;
                #pragma unroll
                for (int c = 0; c < 4; c++) {
                    int base = c * 128 + lane * 4;
                    float4 v = __ldg((const float4*)&a1[base]);
                    s += fmaxf(v.x + att2_s[base + 0], 0.f) * w_s[base + 0];
                    s += fmaxf(v.y + att2_s[base + 1], 0.f) * w_s[base + 1];
                    s += fmaxf(v.z + att2_s[base + 2], 0.f) * w_s[base + 2];
                    s += fmaxf(v.w + att2_s[base + 3], 0.f) * w_s[base + 3];
                }
                #pragma unroll
                for (int o = 16; o; o >>= 1) s += __shfl_down_sync(0xffffffffu, s, o);
                if (lane == 0) att_s[k] = s + b_full[0];
            }
            __syncthreads();

            if (tid < KQ)
                red[tid] = g_mask[b * KQ + tid] ? att_s[tid]
                                                : -__int_as_float(0x7f800000);
            __syncthreads();
            for (int s = 64; s > 0; s >>= 1) {
                if (tid < s) red[tid] = fmaxf(red[tid], red[tid + s]);
                __syncthreads();
            }
            float mx = red[0];
            if (isinf(mx)) mx = 0.f;
            __syncthreads();
            if (tid < KQ) {
                float e = g_mask[b * KQ + tid] ? expf(att_s[tid] - mx) : 0.f;
                alpha_s[tid] = e;
                red[tid] = e;
            }
            __syncthreads();
            for (int s = 64; s > 0; s >>= 1) {
                if (tid < s) red[tid] += red[tid + s];
                __syncthreads();
            }
            float dsum = red[0];
            float inv = (dsum > 0.f) ? 1.f / fmaxf(dsum, 1e-30f) : 0.f;
            __syncthreads();
            if (tid < KQ) alpha_s[tid] *= inv;
            __syncthreads();

            {
                int v = tid & (VDQ - 1), q = tid >> 7;
                const float* eb = enc + (size_t)b * KQ * VDQ;
                float s = 0.f;
                #pragma unroll 4
                for (int k = q * 64; k < q * 64 + 64; k++)
                    s += alpha_s[k] * __ldg(&eb[k * VDQ + v]);
                part[tid] = s;
            }
            __syncthreads();

            bool active = (t < lang_len[b]);
            if (tid < VDQ) {
                float aw = part[tid] + part[tid + 128];
                float gv = b_fbeta[tid];
                #pragma unroll
                for (int s = 0; s < NSPLIT; s++)
                    gv += __ldcg(&g_Yp[((size_t)s * BQ + b) * YDIM + 512 + tid]);
                __stcg(&g_awe[b * VDQ + tid], aw * sigf(gv));
                out_alpha[(size_t)b * TQ * KQ + (size_t)t * KQ + tid]
                    = active ? alpha_s[tid] : 0.f;
            }
        } else {
            // reduce Yp hh partials -> g_Yhh[b][2048]
            int b = bid - 128;
            int col = tid * 8;
            float4 s0 = make_float4(0.f, 0.f, 0.f, 0.f);
            float4 s1 = make_float4(0.f, 0.f, 0.f, 0.f);
            #pragma unroll
            for (int s = 0; s < NSPLIT; s++) {
                const float* p = g_Yp + ((size_t)s * BQ + b) * YDIM + 640 + col;
                float4 v0 = __ldcg((const float4*)p);
                float4 v1 = __ldcg((const float4*)(p + 4));
                s0.x += v0.x; s0.y += v0.y; s0.z += v0.z; s0.w += v0.w;
                s1.x += v1.x; s1.y += v1.y; s1.z += v1.z; s1.w += v1.w;
            }
            __stcg((float4*)&g_Yhh[b * GN + col], s0);
            __stcg((float4*)&g_Yhh[b * GN + col + 4], s1);
        }
        grid_bar((++round) * GRID_P);

        // ======================= P3 =======================
        if (bid < 32) {
            int m0 = (bid & 1) * 64;
            int n0v = (bid >> 1) * 128;          // virtual col base, v = j*4+gate
            int v = n0v + ar;
            int wr = (v & 3) * 512 + (v >> 2);   // Wih row
            const float* Brow = Wih + (size_t)wr * XDIM + EQ;   // awe cols [300,428)

            ull acc[4][4];
            #pragma unroll
            for (int i = 0; i < 4; i++)
                #pragma unroll
                for (int p = 0; p < 4; p++) acc[i][p] = 0ull;

            for (int kt = 0; kt < 8; kt++) {
                int k = kt * 16;
                if (tid < 128) {
                    int am = tid >> 1, akk = (tid & 1) * 8;
                    float4 v0 = __ldcg((const float4*)&g_awe[(m0 + am) * VDQ + k + akk]);
                    float4 v1 = __ldcg((const float4*)&g_awe[(m0 + am) * VDQ + k + akk + 4]);
                    As[(akk + 0) * 64 + am] = v0.x; As[(akk + 1) * 64 + am] = v0.y;
                    As[(akk + 2) * 64 + am] = v0.z; As[(akk + 3) * 64 + am] = v0.w;
                    As[(akk + 4) * 64 + am] = v1.x; As[(akk + 5) * 64 + am] = v1.y;
                    As[(akk + 6) * 64 + am] = v1.z; As[(akk + 7) * 64 + am] = v1.w;
                }
                {
                    float4 v0 = __ldg((const float4*)&Brow[k + ak]);
                    float4 v1 = __ldg((const float4*)&Brow[k + ak + 4]);
                    Bs[(ak + 0) * 128 + ar] = v0.x; Bs[(ak + 1) * 128 + ar] = v0.y;
                    Bs[(ak + 2) * 128 + ar] = v0.z; Bs[(ak + 3) * 128 + ar] = v0.w;
                    Bs[(ak + 4) * 128 + ar] = v1.x; Bs[(ak + 5) * 128 + ar] = v1.y;
                    Bs[(ak + 6) * 128 + ar] = v1.z; Bs[(ak + 7) * 128 + ar] = v1.w;
                }
                __syncthreads();
                #pragma unroll
                for (int kk = 0; kk < 16; kk++) {
                    float4 av = *(const float4*)&As[kk * 64 + ty * 4];
                    const ull* bp = (const ull*)&Bs[kk * 128 + tx * 8];
                    ull b0 = bp[0], b1 = bp[1], b2 = bp[2], b3 = bp[3];
                    ull pa;
                    pa = pk2(av.x, av.x); fma2(acc[0][0], pa, b0); fma2(acc[0][1], pa, b1); fma2(acc[0][2], pa, b2); fma2(acc[0][3], pa, b3);
                    pa = pk2(av.y, av.y); fma2(acc[1][0], pa, b0); fma2(acc[1][1], pa, b1); fma2(acc[1][2], pa, b2); fma2(acc[1][3], pa, b3);
                    pa = pk2(av.z, av.z); fma2(acc[2][0], pa, b0); fma2(acc[2][1], pa, b1); fma2(acc[2][2], pa, b2); fma2(acc[2][3], pa, b3);
                    pa = pk2(av.w, av.w); fma2(acc[3][0], pa, b0); fma2(acc[3][1], pa, b1); fma2(acc[3][2], pa, b2); fma2(acc[3][3], pa, b3);
                }
                __syncthreads();
            }

            // epilogue: thread covers vcols n0v + tx*8 .. +7 = j0,j0+1 x gates 0..3
            int j0 = (n0v >> 2) + tx * 2;
            float2 bi[4], bh2[4];
            #pragma unroll
            for (int g = 0; g < 4; g++) {
                bi[g] = *(const float2*)&b_ih[g * DQ + j0];
                bh2[g] = *(const float2*)&b_hh[g * DQ + j0];
            }
            #pragma unroll
            for (int i = 0; i < 4; i++) {
                int b = m0 + ty * 4 + i;
                const float* Gv = (t == 0) ? g_Ginit
                    : g_Gv + (size_t)__ldg(&lang_idx[b * TQ + (t - 1)]) * GN;
                float ga[8];
                ga[0] = lo32(acc[i][0]); ga[1] = hi32(acc[i][0]);
                ga[2] = lo32(acc[i][1]); ga[3] = hi32(acc[i][1]);
                ga[4] = lo32(acc[i][2]); ga[5] = hi32(acc[i][2]);
                ga[6] = lo32(acc[i][3]); ga[7] = hi32(acc[i][3]);
                float gate[2][4];
                #pragma unroll
                for (int g = 0; g < 4; g++) {
                    float2 gv = *(const float2*)&Gv[g * DQ + j0];
                    float2 gr = *(const float2*)&g_Gref[b * GN + g * DQ + j0];
                    float2 yh; 
                    yh.x = __ldcg(&g_Yhh[b * GN + g * DQ + j0]);
                    yh.y = __ldcg(&g_Yhh[b * GN + g * DQ + j0 + 1]);
                    gate[0][g] = ga[0 * 4 + g] + gv.x + gr.x + yh.x + bi[g].x + bh2[g].x;
                    gate[1][g] = ga[1 * 4 + g] + gv.y + gr.y + yh.y + bi[g].y + bh2[g].y;
                }
                bool act = t < lang_len[b];
                #pragma unroll
                for (int jj = 0; jj < 2; jj++) {
                    int j = j0 + jj;
                    float c_old = __ldcg(&g_c[b * DQ + j]);
                    float cn = sigf(gate[jj][1]) * c_old
                             + sigf(gate[jj][0]) * tanhf(gate[jj][2]);
                    float hn = sigf(gate[jj][3]) * tanhf(cn);
                    float h_prev = __ldcg(&g_h[b * DQ + j]);
                    float h_out = act ? hn : h_prev;
                    if (act) {
                        __stcg(&g_c[b * DQ + j], cn);
                        __stcg(&g_h[b * DQ + j], hn);
                    }
                    g_hstore[((size_t)t * BQ + b) * DQ + j] = h_out;
                }
            }
        }
        if (t != TQ - 1) grid_bar((++round) * GRID_P);
    }

    // done protocol (reset counters for next graph replay)
    __syncthreads();
    __threadfence();
    if (tid == 0) {
        asm volatile("red.release.gpu.global.add.u32 [%0], %1;"
                     :: "l"(&g_done), "r"(1u) : "memory");
        if (bid == 0) {
            unsigned v;
            do {
                asm volatile("ld.acquire.gpu.global.u32 %0, [%1];"
                             : "=r"(v) : "l"(&g_done) : "memory");
            } while (v < (unsigned)GRID_P);
            asm volatile("st.global.cg.u32 [%0], %1;" :: "l"(&g_bar), "r"(0u) : "memory");
            __threadfence();
            asm volatile("st.release.gpu.global.u32 [%0], %1;"
                         :: "l"(&g_done), "r"(0u) : "memory");
        }
    }
}

// ------------------------- final transpose [T,B,V] -> [B,V,T] ----------------
__global__ void transpose_preds(float* __restrict__ out)
{
    __shared__ float tile[32][33];
    int b = blockIdx.x;
    int v0 = blockIdx.y * 32;
    int tx = threadIdx.x, ty = threadIdx.y;
    tile[ty][tx] = g_predsT[(size_t)ty * BQ * VQ + (size_t)b * VQ + v0 + tx];
    __syncthreads();
    out[(size_t)b * VQ * TQ + (size_t)(v0 + ty) * TQ + tx] = tile[tx][ty];
}

// ------------------------- launch ---------------------------------------------
extern "C" void kernel_launch(void* const* d_in, const int* in_sizes, int n_in,
                              void* d_out, int out_size)
{
    const float* enc       = (const float*)d_in[0];
    const float* ref_obj   = (const float*)d_in[1];
    const float* obj_sc    = (const float*)d_in[2];
    const float* center    = (const float*)d_in[3];
    const float* xyz       = (const float*)d_in[4];
    const int*   lang_idx  = (const int*)d_in[5];
    const int*   lang_len  = (const int*)d_in[6];
    const float* emb_tab   = (const float*)d_in[7];
    const float* init_emb  = (const float*)d_in[8];
    const float* W_enc_att = (const float*)d_in[9];
    const float* b_enc_att = (const float*)d_in[10];
    const float* W_dec_att = (const float*)d_in[11];
    const float* b_dec_att = (const float*)d_in[12];
    const float* w_full    = (const float*)d_in[13];
    const float* b_full    = (const float*)d_in[14];
    const float* W_ih      = (const float*)d_in[15];
    const float* b_ih      = (const float*)d_in[16];
    const float* W_hh      = (const float*)d_in[17];
    const float* b_hh      = (const float*)d_in[18];
    const float* W_init_h  = (const float*)d_in[19];
    const float* b_init_h  = (const float*)d_in[20];
    const float* W_init_c  = (const float*)d_in[21];
    const float* b_init_c  = (const float*)d_in[22];
    const float* W_fbeta   = (const float*)d_in[23];
    const float* b_fbeta   = (const float*)d_in[24];
    const float* W_fc      = (const float*)d_in[25];
    const float* b_fc      = (const float*)d_in[26];

    float* out       = (float*)d_out;
    float* out_alpha = out + (size_t)BQ * VQ * TQ;
    float* out_mask  = out_alpha + (size_t)BQ * TQ * KQ;

    float *p_att1, *p_hstore, *p_predsT, *p_Gv, *p_Gref;
    cudaGetSymbolAddress((void**)&p_att1,   g_att1);
    cudaGetSymbolAddress((void**)&p_hstore, g_hstore);
    cudaGetSymbolAddress((void**)&p_predsT, g_predsT);
    cudaGetSymbolAddress((void**)&p_Gv,     g_Gv);
    cudaGetSymbolAddress((void**)&p_Gref,   g_Gref);

    // 1: fused precompute (mask | init | Ginit)
    fused_pre<<<264, 256>>>(obj_sc, center, xyz, enc, ref_obj, init_emb,
                            W_ih, out_mask);
    // 2: h0/c0
    init_hc<<<dim3(16, 4), 256>>>(W_init_h, b_init_h, W_init_c, b_init_c);
    // 3: att1 [16384,512] = enc @ W_enc_att^T
    gemm128<<<dim3(4, 128), 256>>>(enc, VDQ, W_enc_att, VDQ, b_enc_att,
                                   p_att1, AQ, BQ * KQ, AQ, VDQ, nullptr);
    // 4: G_vocab [4000,2048] = emb_table @ Wih[:, :300]^T
    gemm128<<<dim3(16, 32), 256>>>(emb_tab, EQ, W_ih, XDIM, nullptr,
                                   p_Gv, GN, VQ, GN, EQ, nullptr);
    // 5: G_ref [128,2048] = ref_obj @ Wih[:, 428:684]^T
    gemm128<<<dim3(16, 1), 256>>>(ref_obj, ODQ, W_ih + EQ + VDQ, XDIM, nullptr,
                                  p_Gref, GN, BQ, GN, ODQ, nullptr);
    // 6: the 32-step recurrence
    decoder_loop<<<GRID_P, 256>>>(enc, W_dec_att, W_fbeta, W_hh,
                                  b_dec_att, b_fbeta, w_full, b_full,
                                  W_ih, b_ih, b_hh, lang_idx, lang_len,
                                  out_alpha);
    // 7: fc [4096,4000] = hstore @ W_fc^T + b_fc
    gemm128<<<dim3(32, 32), 256>>>(p_hstore, DQ, W_fc, DQ, b_fc,
                                   p_predsT, VQ, TQ * BQ, VQ, DQ, lang_len);
    // 8: [T,B,V] -> [B,V,T]
    transpose_preds<<<dim3(BQ, VQ / 32), dim3(32, 32)>>>(out);
}